// round 13
// baseline (speedup 1.0000x reference)
#include <cuda_runtime.h>
#include <cuda_bf16.h>
#include <math.h>
#include <stdint.h>

#define BATCH 16
#define TLEN 800
#define DDIM 512
#define VOC 4000
#define VPAD 4096
#define LMAX 100
#define SEXT 201
#define NEMIT 101
#define NROWS (BATCH * TLEN)
#define NTILES 32
#define NMTILES 100
#define GSTRIDE 104
#define NEGV (-1e30f)

#define KCHUNK 64
#define NKC 8
#define TILE_BYTES 16384
#define STAGE_BYTES 32768
#define NSTAGE 3
#define DYN_SMEM (NSTAGE * STAGE_BYTES)

#define PREP_CONV   1600
#define PREP_TRANSW 2048
#define PREP_INIT   250
#define PREP_BLOCKS (PREP_CONV + PREP_TRANSW + PREP_INIT)

// ---------------- device scratch ----------------
__device__ __align__(16) __nv_bfloat16 g_Abf[(size_t)NROWS * DDIM];
__device__ __align__(16) __nv_bfloat16 g_Wt[(size_t)VPAD * DDIM];
__device__ float g_pmax[NROWS * NTILES];
__device__ float g_psum[NROWS * NTILES];
__device__ float g_gath[(size_t)NROWS * GSTRIDE];
__device__ float g_emit[(size_t)NROWS * NEMIT];
__device__ int   g_slot[BATCH * VOC];
__device__ int   g_cnt[NMTILES];
__device__ float g_loss[BATCH];

// ---------------- inline index helpers ---------------------------------
__device__ __forceinline__ int sum_hlens(const int* __restrict__ hlens) {
    int s = 0;
#pragma unroll
    for (int i = 0; i < BATCH; i++) s += __ldg(&hlens[i]);
    return s;
}
__device__ __forceinline__ int batch_of(int row, const int* __restrict__ hlens) {
    int off = 0, b = 0;
#pragma unroll
    for (int i = 0; i < BATCH; i++) {
        int nx = off + __ldg(&hlens[i]);
        if (row >= nx) { off = nx; b = i + 1; }
    }
    return b;
}
__device__ __forceinline__ int off_of_batch(int b, const int* __restrict__ hlens) {
    int off = 0;
#pragma unroll
    for (int i = 0; i < BATCH; i++)
        if (i < b) off += __ldg(&hlens[i]);
    return off;
}

// ---------------- PTX helpers (compute_103-legal) ----------------------
__device__ __forceinline__ void ldsm4(uint32_t* r, uint32_t addr) {
    asm volatile("ldmatrix.sync.aligned.m8n8.x4.shared.b16 {%0,%1,%2,%3}, [%4];"
                 : "=r"(r[0]), "=r"(r[1]), "=r"(r[2]), "=r"(r[3]) : "r"(addr));
}
__device__ __forceinline__ void mma16816(float* d, const uint32_t* a,
                                         uint32_t b0, uint32_t b1) {
    asm volatile(
        "mma.sync.aligned.m16n8k16.row.col.f32.bf16.bf16.f32 "
        "{%0,%1,%2,%3}, {%4,%5,%6,%7}, {%8,%9}, {%0,%1,%2,%3};"
        : "+f"(d[0]), "+f"(d[1]), "+f"(d[2]), "+f"(d[3])
        : "r"(a[0]), "r"(a[1]), "r"(a[2]), "r"(a[3]), "r"(b0), "r"(b1));
}
__device__ __forceinline__ int ld_acq(const int* p) {
    int v;
    asm volatile("ld.acquire.cta.b32 %0, [%1];" : "=r"(v) : "l"(p) : "memory");
    return v;
}
__device__ __forceinline__ void st_rel(int* p, int v) {
    asm volatile("st.release.cta.b32 [%0], %1;" :: "l"(p), "r"(v) : "memory");
}
#define CP16(dst, src) \
    asm volatile("cp.async.cg.shared.global [%0], [%1], 16;" :: "r"(dst), "l"(src))
#define CPCOMMIT() asm volatile("cp.async.commit_group;")
#define CPWAIT1()  asm volatile("cp.async.wait_group 1;")

// ---------------- kernel 0: fused prep (convA + transW + init) ---------
__global__ __launch_bounds__(256) void prep_kernel(const float* __restrict__ src,
                                                   const float* __restrict__ W,
                                                   const int* __restrict__ hlens) {
    const int bid = blockIdx.x;
    const int tid = threadIdx.x;

    if (bid < PREP_CONV) {
        int r = bid * 8 + (tid >> 5);
        int lane = tid & 31;
        int b = r / TLEN, t = r - b * TLEN;
        if (t >= __ldg(&hlens[b])) return;
        int dst = off_of_batch(b, hlens) + t;
        const float* p = src + (size_t)r * DDIM;
        __nv_bfloat16* q = g_Abf + (size_t)dst * DDIM;
#pragma unroll
        for (int i = 0; i < 4; i++) {
            float4 v = *(const float4*)(p + lane * 4 + i * 128);
            *(__nv_bfloat162*)(q + lane * 4 + i * 128)     = __floats2bfloat162_rn(v.x, v.y);
            *(__nv_bfloat162*)(q + lane * 4 + i * 128 + 2) = __floats2bfloat162_rn(v.z, v.w);
        }
    } else if (bid < PREP_CONV + PREP_TRANSW) {
        __shared__ float sm[32][33];
        int idx = bid - PREP_CONV;
        int v0 = (idx & 127) * 32, k0 = (idx >> 7) * 32;
        int tx = tid & 31, ty = tid >> 5;
#pragma unroll
        for (int r = 0; r < 4; r++) {
            int k = k0 + ty + r * 8, v = v0 + tx;
            sm[ty + r * 8][tx] = (v < VOC) ? W[(size_t)k * VOC + v] : 0.f;
        }
        __syncthreads();
#pragma unroll
        for (int r = 0; r < 4; r++) {
            int v = v0 + ty + r * 8, k = k0 + tx;
            g_Wt[(size_t)v * DDIM + k] = __float2bfloat16(sm[tx][ty + r * 8]);
        }
    } else {
        int i = (bid - PREP_CONV - PREP_TRANSW) * 256 + tid;
        if (i < BATCH * VOC) g_slot[i] = -1;
        if (i < NMTILES) g_cnt[i] = 0;
    }
}

// ---------------- kernel 0b: write label slots -------------------------
__global__ void write_slot_kernel(const int* __restrict__ ys_pad) {
    int b = blockIdx.x;
    int j = threadIdx.x;
    if (j < LMAX) g_slot[b * VOC + ys_pad[b * LMAX + j]] = j + 1;
    if (j == LMAX) g_slot[b * VOC + 0] = 0;
}

// ---------------- kernel 1: GEMM + fused LSE/emit (last-arriver) -------
__global__ __launch_bounds__(256, 2)
void mma_gemm_kernel(const float* __restrict__ bias,
                     const int* __restrict__ hlens,
                     const int* __restrict__ ys_pad) {
    extern __shared__ __align__(128) char dynbuf[];
    __shared__ float bias_s[128];
    __shared__ int   slot_s[256];
    __shared__ int   info_s[128];
    __shared__ float redM[128 * 5];
    __shared__ float redS[128 * 5];
    __shared__ float lse_sh[128];
    __shared__ int   is_last;

    const int n0 = blockIdx.x * 128, m0 = blockIdx.y * 128;
    const int nlive = sum_hlens(hlens);
    if (m0 >= nlive) return;

    const int rb0 = batch_of(m0, hlens);
    const int rlast = (m0 + 127 < nlive) ? (m0 + 127) : (nlive - 1);
    const int rb1 = batch_of(rlast, hlens);

    const uint32_t sbD = (uint32_t)__cvta_generic_to_shared(dynbuf);
    const int tid = threadIdx.x;
    const int lane = tid & 31, wid = tid >> 5;
    const int wm = wid >> 2, wn = wid & 3;

    const int crow = tid >> 3;
    const int cc8  = tid & 7;
    const uint32_t cxr = (uint32_t)((crow & 7) << 4);
    const uint32_t cdst = (uint32_t)(crow * 128 + ((cc8 * 16) ^ cxr));
    const __nv_bfloat16* Ab = g_Abf + (size_t)m0 * DDIM;
    const __nv_bfloat16* Bb = g_Wt  + (size_t)n0 * DDIM;

#pragma unroll
    for (int s = 0; s < NSTAGE - 1; s++) {
        uint32_t dst = sbD + s * STAGE_BYTES;
        int k0 = s * KCHUNK;
#pragma unroll
        for (int i = 0; i < 4; i++) {
            CP16(dst + cdst + i * (32 * 128),
                 Ab + (size_t)(crow + 32 * i) * DDIM + k0 + cc8 * 8);
            CP16(dst + TILE_BYTES + cdst + i * (32 * 128),
                 Bb + (size_t)(crow + 32 * i) * DDIM + k0 + cc8 * 8);
        }
        CPCOMMIT();
    }

    if (tid < 128) {
        int gc = n0 + tid;
        bias_s[tid]       = (gc < VOC) ? bias[gc] : 0.f;
        slot_s[tid]       = (gc < VOC) ? g_slot[rb0 * VOC + gc] : -1;
        slot_s[128 + tid] = (gc < VOC) ? g_slot[rb1 * VOC + gc] : -1;
        info_s[tid]       = batch_of(m0 + tid, hlens);
    }

    float acc[4][16];
#pragma unroll
    for (int i = 0; i < 4; i++)
#pragma unroll
        for (int j = 0; j < 16; j++) acc[i][j] = 0.f;

    const int arow = wm * 64 + (lane & 15);
    const int brow = wn * 32 + (lane & 15);
    const uint32_t axr = (uint32_t)((arow & 7) << 4);
    const uint32_t bxr = (uint32_t)((brow & 7) << 4);
    const uint32_t ahi = (uint32_t)((lane >> 4) << 4);

#pragma unroll
    for (int kc = 0; kc < NKC; kc++) {
        CPWAIT1();
        __syncthreads();

        int ks = kc + NSTAGE - 1;
        if (ks < NKC) {
            uint32_t dst = sbD + (ks % 3) * STAGE_BYTES;
            int k0 = ks * KCHUNK;
#pragma unroll
            for (int i = 0; i < 4; i++) {
                CP16(dst + cdst + i * (32 * 128),
                     Ab + (size_t)(crow + 32 * i) * DDIM + k0 + cc8 * 8);
                CP16(dst + TILE_BYTES + cdst + i * (32 * 128),
                     Bb + (size_t)(crow + 32 * i) * DDIM + k0 + cc8 * 8);
            }
        }
        CPCOMMIT();

        const uint32_t base = sbD + (kc % 3) * STAGE_BYTES;
#pragma unroll
        for (int h = 0; h < 4; h++) {
            const uint32_t acol = ((uint32_t)(h * 32) | ahi) ^ axr;
            const uint32_t bcol = ((uint32_t)(h * 32) | ahi) ^ bxr;
            uint32_t af[4][4], bf[2][4];
#pragma unroll
            for (int mf = 0; mf < 4; mf++)
                ldsm4(af[mf], base + (uint32_t)((arow + mf * 16) * 128) + acol);
#pragma unroll
            for (int jg = 0; jg < 2; jg++)
                ldsm4(bf[jg], base + TILE_BYTES + (uint32_t)((brow + jg * 16) * 128) + bcol);
#pragma unroll
            for (int mf = 0; mf < 4; mf++) {
#pragma unroll
                for (int jg = 0; jg < 2; jg++) {
                    mma16816(&acc[mf][(jg * 2 + 0) * 4], af[mf], bf[jg][0], bf[jg][2]);
                    mma16816(&acc[mf][(jg * 2 + 1) * 4], af[mf], bf[jg][1], bf[jg][3]);
                }
            }
        }
    }

    // ---- epilogue: bias + online max/sumexp + label gather ----
    float biasv[8]; bool validv[8]; int sl0[8], sl1[8];
#pragma unroll
    for (int nf = 0; nf < 4; nf++)
#pragma unroll
        for (int e = 0; e < 2; e++) {
            int idx = nf * 2 + e;
            int c = wn * 32 + nf * 8 + (lane & 3) * 2 + e;
            biasv[idx]  = bias_s[c];
            validv[idx] = (n0 + c) < VOC;
            sl0[idx] = slot_s[c];
            sl1[idx] = slot_s[128 + c];
        }
#pragma unroll
    for (int mf = 0; mf < 4; mf++)
#pragma unroll
        for (int k = 0; k < 16; k++)
            acc[mf][k] += biasv[(k >> 2) * 2 + (k & 1)];

#pragma unroll
    for (int mf = 0; mf < 4; mf++) {
#pragma unroll
        for (int half = 0; half < 2; half++) {
            int r = wm * 64 + mf * 16 + half * 8 + (lane >> 2);
            int grow = m0 + r;
            bool live = grow < nlive;
            int bb = (info_s[r] != rb0) ? 1 : 0;
            float m = -3.4e38f, s = 0.f;
            if (live) {
#pragma unroll
                for (int ci = 0; ci < 8; ci++) {
                    float v = acc[mf][(ci >> 1) * 4 + half * 2 + (ci & 1)];
                    if (validv[ci]) m = fmaxf(m, v);
                }
#pragma unroll
                for (int ci = 0; ci < 8; ci++) {
                    float v = acc[mf][(ci >> 1) * 4 + half * 2 + (ci & 1)];
                    if (validv[ci]) {
                        s += __expf(v - m);
                        int sl = bb ? sl1[ci] : sl0[ci];
                        if (sl >= 0) g_gath[(size_t)grow * GSTRIDE + sl] = v;
                    }
                }
            }
#pragma unroll
            for (int off = 1; off <= 2; off <<= 1) {
                float om = __shfl_xor_sync(~0u, m, off);
                float os = __shfl_xor_sync(~0u, s, off);
                float nm = fmaxf(m, om);
                s = s * __expf(m - nm) + os * __expf(om - nm);
                m = nm;
            }
            if ((lane & 3) == 0) { redM[r * 5 + wn] = m; redS[r * 5 + wn] = s; }
        }
    }
    __syncthreads();
    if (tid < 128) {
        float M = redM[tid * 5 + 0], S = redS[tid * 5 + 0];
#pragma unroll
        for (int w = 1; w < 4; w++) {
            float m2 = redM[tid * 5 + w], s2 = redS[tid * 5 + w];
            float Mn = fmaxf(M, m2);
            S = S * __expf(M - Mn) + s2 * __expf(m2 - Mn);
            M = Mn;
        }
        g_pmax[(m0 + tid) * NTILES + blockIdx.x] = M;
        g_psum[(m0 + tid) * NTILES + blockIdx.x] = S;
    }

    // ---- last-arriver fused LSE + emit for this m-tile ----
    __threadfence();
    __syncthreads();
    if (tid == 0)
        is_last = (atomicAdd(&g_cnt[blockIdx.y], 1) == NTILES - 1);
    __syncthreads();
    if (!is_last) return;
    __threadfence();

    if (tid < 128) {
        int row = m0 + tid;
        if (row < nlive) {
            float M = -3.4e38f, S = 0.f;
#pragma unroll 4
            for (int w = 0; w < NTILES; w++) {
                float pm = g_pmax[row * NTILES + w];
                float ps = g_psum[row * NTILES + w];
                float Mn = fmaxf(M, pm);
                S = S * __expf(M - Mn) + ps * __expf(pm - Mn);
                M = Mn;
            }
            lse_sh[tid] = M + __logf(S);
        }
    }
    __syncthreads();
    for (int idx = tid; idx < 128 * NEMIT; idx += 256) {
        int r = idx / NEMIT, j = idx - r * NEMIT;
        int row = m0 + r;
        if (row < nlive) {
            int b = info_s[r];
            int col = (j == 0) ? 0 : ys_pad[b * LMAX + j - 1];
            int slot = g_slot[b * VOC + col];
            g_emit[(size_t)row * NEMIT + j] =
                g_gath[(size_t)row * GSTRIDE + slot] - lse_sh[r];
        }
    }
}

// ---------------- kernel 2: CTC recursion (warp-pipelined, no bar) -----
__global__ __launch_bounds__(224) void ctc_kernel(const int* __restrict__ hlens,
                                                  const int* __restrict__ ys_pad,
                                                  const int* __restrict__ ys_lens) {
    const int b = blockIdx.x;
    const int tid = threadIdx.x;
    const int w = tid >> 5, lane = tid & 31;
    const int s = tid;
    __shared__ float ring[7][32][2];   // [warp][step&31][{lane30,lane31}]
    __shared__ int   cnt[8];           // per-warp published step; cnt[7]=inf
    __shared__ float alfin[SEXT];

    const int roff = off_of_batch(b, hlens);
    const float* eb = g_emit + (size_t)roff * NEMIT;
    const bool act = s < SEXT;
    const int j = (s & 1) ? ((s >> 1) + 1) : 0;

    bool skip = false;
    if (act && (s & 1) && s >= 3) {
        skip = ys_pad[b * LMAX + (s >> 1)] != ys_pad[b * LMAX + (s >> 1) - 1];
    }

    float a = act ? ((s < 2) ? eb[j] : NEGV) : NEGV;

    // initial boundary publish (step 0)
    {
        float a30 = __shfl_sync(~0u, a, 30);
        if (lane == 31) {
            ring[w][0][0] = a30;
            ring[w][0][1] = a;
            cnt[w] = 0;
        }
    }
    if (tid == 0) cnt[7] = 0x40000000;
    __syncthreads();

    const int hl = hlens[b];
    float eA = (act && hl > 1) ? eb[(size_t)1 * NEMIT + j] : NEGV;
    float eB = (act && hl > 2) ? eb[(size_t)2 * NEMIT + j] : NEGV;

    for (int t = 1; t < hl; t++) {
        float e = eA;
        eA = eB;
        if (act && t + 2 < hl) eB = eb[(size_t)(t + 2) * NEMIT + j];

        // wait: upstream (w-1) published t-1; downstream (w+1) consumed ring slot
        {
            unsigned ok;
            do {
                bool my_ok = true;
                if (lane == 0 && w > 0)  my_ok = (ld_acq(&cnt[w - 1]) >= t - 1);
                if (lane == 31)          my_ok = (ld_acq(&cnt[w + 1]) >= t - 24);
                ok = __all_sync(~0u, my_ok);
            } while (!ok);
        }

        // boundary fetch (lane 0 does the ordered load, broadcast)
        float r30 = NEGV, r31 = NEGV;
        if (lane == 0 && w > 0) {
            const float* rp = &ring[w - 1][(t - 1) & 31][0];
            r30 = rp[0];
            r31 = rp[1];
        }
        float am1 = __shfl_up_sync(~0u, a, 1);
        float am2 = __shfl_up_sync(~0u, a, 2);
        float r30b = __shfl_sync(~0u, r30, 0);
        float r31b = __shfl_sync(~0u, r31, 0);
        if (lane == 0) { am1 = r31b; am2 = r30b; }
        if (lane == 1) { am2 = r31b; }

        float x2 = skip ? am2 : NEGV;
        float m = fmaxf(a, fmaxf(am1, x2));
        float sum = __expf(a - m) + __expf(am1 - m) + __expf(x2 - m);
        float anew = m + __logf(sum) + e;
        a = act ? anew : NEGV;

        // publish boundary (single-thread stores -> release valid)
        float a30 = __shfl_sync(~0u, a, 30);
        if (lane == 31) {
            float* rp = &ring[w][t & 31][0];
            rp[0] = a30;
            rp[1] = a;
            st_rel(&cnt[w], t);
        }
    }

    if (act) alfin[s] = a;
    __syncthreads();

    if (tid == 0) {
        int L = ys_lens[b];
        int idx = 2 * L;
        float aL = alfin[idx];
        float aP = alfin[idx - 1];
        float m = fmaxf(aL, aP);
        float loss = -(m + __logf(__expf(aL - m) + __expf(aP - m)));
        if (!isfinite(loss) || loss >= 1e29f) loss = 0.f;
        g_loss[b] = loss;
    }
}

// ---------------- kernel 3: final reduce --------------------------------
__global__ void finalize_kernel(float* __restrict__ out) {
    float sum = 0.f;
    for (int i = 0; i < BATCH; i++) sum += g_loss[i];
    out[0] = sum / (float)BATCH;
}

// ---------------- launch --------------------------------------------------
extern "C" void kernel_launch(void* const* d_in, const int* in_sizes, int n_in,
                              void* d_out, int out_size) {
    const float* hs     = (const float*)d_in[0];
    const float* Wm     = (const float*)d_in[1];
    const float* bias   = (const float*)d_in[2];
    const int* hlens    = (const int*)d_in[3];
    const int* ys_pad   = (const int*)d_in[4];
    const int* ys_lens  = (const int*)d_in[5];
    float* out = (float*)d_out;

    cudaFuncSetAttribute(mma_gemm_kernel,
                         cudaFuncAttributeMaxDynamicSharedMemorySize, DYN_SMEM);

    prep_kernel<<<PREP_BLOCKS, 256>>>(hs, Wm, hlens);
    write_slot_kernel<<<BATCH, 128>>>(ys_pad);

    dim3 gemm_grid(NTILES, NROWS / 128);
    mma_gemm_kernel<<<gemm_grid, 256, DYN_SMEM>>>(bias, hlens, ys_pad);

    ctc_kernel<<<BATCH, 224>>>(hlens, ys_pad, ys_lens);
    finalize_kernel<<<1, 1>>>(out);
}

// round 14
// speedup vs baseline: 1.0340x; 1.0340x over previous
#include <cuda_runtime.h>
#include <cuda_bf16.h>
#include <math.h>
#include <stdint.h>

#define BATCH 16
#define TLEN 800
#define DDIM 512
#define VOC 4000
#define VPAD 4096
#define LMAX 100
#define SEXT 201
#define NEMIT 101
#define NROWS (BATCH * TLEN)
#define NTILES 32
#define NMTILES 100
#define GSTRIDE 104
#define NEGV (-1e30f)

#define KCHUNK 64
#define NKC 8
#define TILE_BYTES 16384
#define STAGE_BYTES 32768
#define NSTAGE 3
#define DYN_SMEM (NSTAGE * STAGE_BYTES)

#define PREP_CONV   1600
#define PREP_TRANSW 2048
#define PREP_INIT   250
#define PREP_BLOCKS (PREP_CONV + PREP_TRANSW + PREP_INIT)

// ---------------- device scratch ----------------
__device__ __align__(16) __nv_bfloat16 g_Abf[(size_t)NROWS * DDIM];
__device__ __align__(16) __nv_bfloat16 g_Wt[(size_t)VPAD * DDIM];
__device__ float g_pmax[NROWS * NTILES];
__device__ float g_psum[NROWS * NTILES];
__device__ float g_gath[(size_t)NROWS * GSTRIDE];
__device__ float g_emit[(size_t)NROWS * NEMIT];
__device__ int   g_slot[BATCH * VOC];
__device__ int   g_cnt[NMTILES];
__device__ float g_loss[BATCH];

// ---------------- inline index helpers ---------------------------------
__device__ __forceinline__ int sum_hlens(const int* __restrict__ hlens) {
    int s = 0;
#pragma unroll
    for (int i = 0; i < BATCH; i++) s += __ldg(&hlens[i]);
    return s;
}
__device__ __forceinline__ int batch_of(int row, const int* __restrict__ hlens) {
    int off = 0, b = 0;
#pragma unroll
    for (int i = 0; i < BATCH; i++) {
        int nx = off + __ldg(&hlens[i]);
        if (row >= nx) { off = nx; b = i + 1; }
    }
    return b;
}
__device__ __forceinline__ int off_of_batch(int b, const int* __restrict__ hlens) {
    int off = 0;
#pragma unroll
    for (int i = 0; i < BATCH; i++)
        if (i < b) off += __ldg(&hlens[i]);
    return off;
}

// ---------------- PTX helpers (compute_103-legal) ----------------------
__device__ __forceinline__ void ldsm4(uint32_t* r, uint32_t addr) {
    asm volatile("ldmatrix.sync.aligned.m8n8.x4.shared.b16 {%0,%1,%2,%3}, [%4];"
                 : "=r"(r[0]), "=r"(r[1]), "=r"(r[2]), "=r"(r[3]) : "r"(addr));
}
__device__ __forceinline__ void mma16816(float* d, const uint32_t* a,
                                         uint32_t b0, uint32_t b1) {
    asm volatile(
        "mma.sync.aligned.m16n8k16.row.col.f32.bf16.bf16.f32 "
        "{%0,%1,%2,%3}, {%4,%5,%6,%7}, {%8,%9}, {%0,%1,%2,%3};"
        : "+f"(d[0]), "+f"(d[1]), "+f"(d[2]), "+f"(d[3])
        : "r"(a[0]), "r"(a[1]), "r"(a[2]), "r"(a[3]), "r"(b0), "r"(b1));
}
#define CP16(dst, src) \
    asm volatile("cp.async.cg.shared.global [%0], [%1], 16;" :: "r"(dst), "l"(src))
#define CPCOMMIT() asm volatile("cp.async.commit_group;")
#define CPWAIT1()  asm volatile("cp.async.wait_group 1;")

// ---------------- kernel 0: fused prep (convA + transW + init) ---------
__global__ __launch_bounds__(256) void prep_kernel(const float* __restrict__ src,
                                                   const float* __restrict__ W,
                                                   const int* __restrict__ hlens) {
    const int bid = blockIdx.x;
    const int tid = threadIdx.x;

    if (bid < PREP_CONV) {
        int r = bid * 8 + (tid >> 5);
        int lane = tid & 31;
        int b = r / TLEN, t = r - b * TLEN;
        if (t >= __ldg(&hlens[b])) return;
        int dst = off_of_batch(b, hlens) + t;
        const float* p = src + (size_t)r * DDIM;
        __nv_bfloat16* q = g_Abf + (size_t)dst * DDIM;
#pragma unroll
        for (int i = 0; i < 4; i++) {
            float4 v = *(const float4*)(p + lane * 4 + i * 128);
            *(__nv_bfloat162*)(q + lane * 4 + i * 128)     = __floats2bfloat162_rn(v.x, v.y);
            *(__nv_bfloat162*)(q + lane * 4 + i * 128 + 2) = __floats2bfloat162_rn(v.z, v.w);
        }
    } else if (bid < PREP_CONV + PREP_TRANSW) {
        __shared__ float sm[32][33];
        int idx = bid - PREP_CONV;
        int v0 = (idx & 127) * 32, k0 = (idx >> 7) * 32;
        int tx = tid & 31, ty = tid >> 5;
#pragma unroll
        for (int r = 0; r < 4; r++) {
            int k = k0 + ty + r * 8, v = v0 + tx;
            sm[ty + r * 8][tx] = (v < VOC) ? W[(size_t)k * VOC + v] : 0.f;
        }
        __syncthreads();
#pragma unroll
        for (int r = 0; r < 4; r++) {
            int v = v0 + ty + r * 8, k = k0 + tx;
            g_Wt[(size_t)v * DDIM + k] = __float2bfloat16(sm[tx][ty + r * 8]);
        }
    } else {
        int i = (bid - PREP_CONV - PREP_TRANSW) * 256 + tid;
        if (i < BATCH * VOC) g_slot[i] = -1;
        if (i < NMTILES) g_cnt[i] = 0;
    }
}

// ---------------- kernel 0b: write label slots -------------------------
__global__ void write_slot_kernel(const int* __restrict__ ys_pad) {
    int b = blockIdx.x;
    int j = threadIdx.x;
    if (j < LMAX) g_slot[b * VOC + ys_pad[b * LMAX + j]] = j + 1;
    if (j == LMAX) g_slot[b * VOC + 0] = 0;
}

// ---------------- kernel 1: GEMM + fused LSE/emit (last-arriver) -------
__global__ __launch_bounds__(256, 2)
void mma_gemm_kernel(const float* __restrict__ bias,
                     const int* __restrict__ hlens,
                     const int* __restrict__ ys_pad) {
    extern __shared__ __align__(128) char dynbuf[];
    __shared__ float bias_s[128];
    __shared__ int   slot_s[256];
    __shared__ int   info_s[128];
    __shared__ float redM[128 * 5];
    __shared__ float redS[128 * 5];
    __shared__ float lse_sh[128];
    __shared__ int   is_last;

    const int n0 = blockIdx.x * 128, m0 = blockIdx.y * 128;
    const int nlive = sum_hlens(hlens);
    if (m0 >= nlive) return;

    const int rb0 = batch_of(m0, hlens);
    const int rlast = (m0 + 127 < nlive) ? (m0 + 127) : (nlive - 1);
    const int rb1 = batch_of(rlast, hlens);

    const uint32_t sbD = (uint32_t)__cvta_generic_to_shared(dynbuf);
    const int tid = threadIdx.x;
    const int lane = tid & 31, wid = tid >> 5;
    const int wm = wid >> 2, wn = wid & 3;

    const int crow = tid >> 3;
    const int cc8  = tid & 7;
    const uint32_t cxr = (uint32_t)((crow & 7) << 4);
    const uint32_t cdst = (uint32_t)(crow * 128 + ((cc8 * 16) ^ cxr));
    const __nv_bfloat16* Ab = g_Abf + (size_t)m0 * DDIM;
    const __nv_bfloat16* Bb = g_Wt  + (size_t)n0 * DDIM;

#pragma unroll
    for (int s = 0; s < NSTAGE - 1; s++) {
        uint32_t dst = sbD + s * STAGE_BYTES;
        int k0 = s * KCHUNK;
#pragma unroll
        for (int i = 0; i < 4; i++) {
            CP16(dst + cdst + i * (32 * 128),
                 Ab + (size_t)(crow + 32 * i) * DDIM + k0 + cc8 * 8);
            CP16(dst + TILE_BYTES + cdst + i * (32 * 128),
                 Bb + (size_t)(crow + 32 * i) * DDIM + k0 + cc8 * 8);
        }
        CPCOMMIT();
    }

    if (tid < 128) {
        int gc = n0 + tid;
        bias_s[tid]       = (gc < VOC) ? bias[gc] : 0.f;
        slot_s[tid]       = (gc < VOC) ? g_slot[rb0 * VOC + gc] : -1;
        slot_s[128 + tid] = (gc < VOC) ? g_slot[rb1 * VOC + gc] : -1;
        info_s[tid]       = batch_of(m0 + tid, hlens);
    }

    float acc[4][16];
#pragma unroll
    for (int i = 0; i < 4; i++)
#pragma unroll
        for (int j = 0; j < 16; j++) acc[i][j] = 0.f;

    const int arow = wm * 64 + (lane & 15);
    const int brow = wn * 32 + (lane & 15);
    const uint32_t axr = (uint32_t)((arow & 7) << 4);
    const uint32_t bxr = (uint32_t)((brow & 7) << 4);
    const uint32_t ahi = (uint32_t)((lane >> 4) << 4);

#pragma unroll
    for (int kc = 0; kc < NKC; kc++) {
        CPWAIT1();
        __syncthreads();

        int ks = kc + NSTAGE - 1;
        if (ks < NKC) {
            uint32_t dst = sbD + (ks % 3) * STAGE_BYTES;
            int k0 = ks * KCHUNK;
#pragma unroll
            for (int i = 0; i < 4; i++) {
                CP16(dst + cdst + i * (32 * 128),
                     Ab + (size_t)(crow + 32 * i) * DDIM + k0 + cc8 * 8);
                CP16(dst + TILE_BYTES + cdst + i * (32 * 128),
                     Bb + (size_t)(crow + 32 * i) * DDIM + k0 + cc8 * 8);
            }
        }
        CPCOMMIT();

        const uint32_t base = sbD + (kc % 3) * STAGE_BYTES;
#pragma unroll
        for (int h = 0; h < 4; h++) {
            const uint32_t acol = ((uint32_t)(h * 32) | ahi) ^ axr;
            const uint32_t bcol = ((uint32_t)(h * 32) | ahi) ^ bxr;
            uint32_t af[4][4], bf[2][4];
#pragma unroll
            for (int mf = 0; mf < 4; mf++)
                ldsm4(af[mf], base + (uint32_t)((arow + mf * 16) * 128) + acol);
#pragma unroll
            for (int jg = 0; jg < 2; jg++)
                ldsm4(bf[jg], base + TILE_BYTES + (uint32_t)((brow + jg * 16) * 128) + bcol);
#pragma unroll
            for (int mf = 0; mf < 4; mf++) {
#pragma unroll
                for (int jg = 0; jg < 2; jg++) {
                    mma16816(&acc[mf][(jg * 2 + 0) * 4], af[mf], bf[jg][0], bf[jg][2]);
                    mma16816(&acc[mf][(jg * 2 + 1) * 4], af[mf], bf[jg][1], bf[jg][3]);
                }
            }
        }
    }

    // ---- epilogue: bias + online max/sumexp + label gather ----
    float biasv[8]; bool validv[8]; int sl0[8], sl1[8];
#pragma unroll
    for (int nf = 0; nf < 4; nf++)
#pragma unroll
        for (int e = 0; e < 2; e++) {
            int idx = nf * 2 + e;
            int c = wn * 32 + nf * 8 + (lane & 3) * 2 + e;
            biasv[idx]  = bias_s[c];
            validv[idx] = (n0 + c) < VOC;
            sl0[idx] = slot_s[c];
            sl1[idx] = slot_s[128 + c];
        }
#pragma unroll
    for (int mf = 0; mf < 4; mf++)
#pragma unroll
        for (int k = 0; k < 16; k++)
            acc[mf][k] += biasv[(k >> 2) * 2 + (k & 1)];

#pragma unroll
    for (int mf = 0; mf < 4; mf++) {
#pragma unroll
        for (int half = 0; half < 2; half++) {
            int r = wm * 64 + mf * 16 + half * 8 + (lane >> 2);
            int grow = m0 + r;
            bool live = grow < nlive;
            int bb = (info_s[r] != rb0) ? 1 : 0;
            float m = -3.4e38f, s = 0.f;
            if (live) {
#pragma unroll
                for (int ci = 0; ci < 8; ci++) {
                    float v = acc[mf][(ci >> 1) * 4 + half * 2 + (ci & 1)];
                    if (validv[ci]) m = fmaxf(m, v);
                }
#pragma unroll
                for (int ci = 0; ci < 8; ci++) {
                    float v = acc[mf][(ci >> 1) * 4 + half * 2 + (ci & 1)];
                    if (validv[ci]) {
                        s += __expf(v - m);
                        int sl = bb ? sl1[ci] : sl0[ci];
                        if (sl >= 0) g_gath[(size_t)grow * GSTRIDE + sl] = v;
                    }
                }
            }
#pragma unroll
            for (int off = 1; off <= 2; off <<= 1) {
                float om = __shfl_xor_sync(~0u, m, off);
                float os = __shfl_xor_sync(~0u, s, off);
                float nm = fmaxf(m, om);
                s = s * __expf(m - nm) + os * __expf(om - nm);
                m = nm;
            }
            if ((lane & 3) == 0) { redM[r * 5 + wn] = m; redS[r * 5 + wn] = s; }
        }
    }
    __syncthreads();
    if (tid < 128) {
        float M = redM[tid * 5 + 0], S = redS[tid * 5 + 0];
#pragma unroll
        for (int w = 1; w < 4; w++) {
            float m2 = redM[tid * 5 + w], s2 = redS[tid * 5 + w];
            float Mn = fmaxf(M, m2);
            S = S * __expf(M - Mn) + s2 * __expf(m2 - Mn);
            M = Mn;
        }
        g_pmax[(m0 + tid) * NTILES + blockIdx.x] = M;
        g_psum[(m0 + tid) * NTILES + blockIdx.x] = S;
    }

    // ---- last-arriver fused LSE + emit for this m-tile ----
    __threadfence();
    __syncthreads();
    if (tid == 0)
        is_last = (atomicAdd(&g_cnt[blockIdx.y], 1) == NTILES - 1);
    __syncthreads();
    if (!is_last) return;
    __threadfence();

    if (tid < 128) {
        int row = m0 + tid;
        if (row < nlive) {
            float M = -3.4e38f, S = 0.f;
#pragma unroll 4
            for (int w = 0; w < NTILES; w++) {
                float pm = g_pmax[row * NTILES + w];
                float ps = g_psum[row * NTILES + w];
                float Mn = fmaxf(M, pm);
                S = S * __expf(M - Mn) + ps * __expf(pm - Mn);
                M = Mn;
            }
            lse_sh[tid] = M + __logf(S);
        }
    }
    __syncthreads();
    for (int idx = tid; idx < 128 * NEMIT; idx += 256) {
        int r = idx / NEMIT, j = idx - r * NEMIT;
        int row = m0 + r;
        if (row < nlive) {
            int b = info_s[r];
            int col = (j == 0) ? 0 : ys_pad[b * LMAX + j - 1];
            int slot = g_slot[b * VOC + col];
            g_emit[(size_t)row * NEMIT + j] =
                g_gath[(size_t)row * GSTRIDE + slot] - lse_sh[r];
        }
    }
}

// ---------------- kernel 2: CTC forward recursion (single-step) --------
__global__ __launch_bounds__(224) void ctc_kernel(const int* __restrict__ hlens,
                                                  const int* __restrict__ ys_pad,
                                                  const int* __restrict__ ys_lens) {
    const int b = blockIdx.x;
    const int s = threadIdx.x;
    __shared__ float al[2][SEXT + 2];

    const int roff = off_of_batch(b, hlens);
    const float* eb = g_emit + (size_t)roff * NEMIT;
    const bool act = s < SEXT;
    const int j = (s & 1) ? ((s >> 1) + 1) : 0;

    bool skip = false;
    if (act && (s & 1) && s >= 3) {
        int cur  = ys_pad[b * LMAX + (s >> 1)];
        int prev = ys_pad[b * LMAX + (s >> 1) - 1];
        skip = (cur != prev);
    }

    if (s < 2) { al[0][s] = NEGV; al[1][s] = NEGV; }
    if (act) al[0][s + 2] = (s < 2) ? eb[j] : NEGV;

    const int hl = hlens[b];
    float e1 = NEGV;
    if (act && hl > 1) e1 = eb[NEMIT + j];
    __syncthreads();

    int p = 0;
    for (int t = 1; t < hl; t++) {
        float e = e1;
        if (act && t + 1 < hl) e1 = eb[(size_t)(t + 1) * NEMIT + j];

        if (act) {
            float a0 = al[p][s + 2];
            float a1 = al[p][s + 1];
            float a2 = skip ? al[p][s] : NEGV;
            float m = fmaxf(a0, fmaxf(a1, a2));
            float w = __expf(a0 - m) + __expf(a1 - m) + __expf(a2 - m);
            al[1 - p][s + 2] = m + __logf(w) + e;
        }
        __syncthreads();
        p ^= 1;
    }

    if (s == 0) {
        int L = ys_lens[b];
        int idx = 2 * L;
        float aL = al[p][idx + 2];
        float aP = al[p][idx + 1];
        float m = fmaxf(aL, aP);
        float loss = -(m + __logf(__expf(aL - m) + __expf(aP - m)));
        if (!isfinite(loss) || loss >= 1e29f) loss = 0.f;
        g_loss[b] = loss;
    }
}

// ---------------- kernel 3: final reduce --------------------------------
__global__ void finalize_kernel(float* __restrict__ out) {
    float sum = 0.f;
    for (int i = 0; i < BATCH; i++) sum += g_loss[i];
    out[0] = sum / (float)BATCH;
}

// ---------------- launch --------------------------------------------------
extern "C" void kernel_launch(void* const* d_in, const int* in_sizes, int n_in,
                              void* d_out, int out_size) {
    const float* hs     = (const float*)d_in[0];
    const float* Wm     = (const float*)d_in[1];
    const float* bias   = (const float*)d_in[2];
    const int* hlens    = (const int*)d_in[3];
    const int* ys_pad   = (const int*)d_in[4];
    const int* ys_lens  = (const int*)d_in[5];
    float* out = (float*)d_out;

    cudaFuncSetAttribute(mma_gemm_kernel,
                         cudaFuncAttributeMaxDynamicSharedMemorySize, DYN_SMEM);

    prep_kernel<<<PREP_BLOCKS, 256>>>(hs, Wm, hlens);
    write_slot_kernel<<<BATCH, 128>>>(ys_pad);

    dim3 gemm_grid(NTILES, NROWS / 128);
    mma_gemm_kernel<<<gemm_grid, 256, DYN_SMEM>>>(bias, hlens, ys_pad);

    ctc_kernel<<<BATCH, 224>>>(hlens, ys_pad, ys_lens);
    finalize_kernel<<<1, 1>>>(out);
}